// round 5
// baseline (speedup 1.0000x reference)
#include <cuda_runtime.h>
#include <cstdint>
#include <cub/cub.cuh>

// Problem constants
#define C_DIM     4096
#define NUMEL_D   16777216.0
#define MAX_K     4500000               // >= S + R = 4,404,019
#define M_SORT    1310720               // R + 256K slack (candidate sort size, fixed for graph)
#define HIST_BINS (1u << 18)            // ordkey >> 13
#define TEMP_BYTES (96u * 1024u * 1024u)

// Static device scratch (allocation-free per harness rules)
__device__ uint32_t g_ka[MAX_K];        // pack keys -> sort1 key in
__device__ uint32_t g_kb[MAX_K];        // sort1 key out (key-sorted keys)
__device__ uint32_t g_va[MAX_K];        // pack value bits
__device__ uint32_t g_vb[MAX_K];        // sort1 value out (key-ordered value bits)
__device__ unsigned long long g_z[MAX_K]; // per-position zip: (ordkey<<24)|key, ~0 for non-heads
__device__ uint32_t g_hist[HIST_BINS];
__device__ uint32_t g_super[1024];
__device__ uint32_t g_B[1];
__device__ int      g_num[1];
__device__ unsigned char g_temp[TEMP_BYTES];
// temp arena layout: [0,16MB) cand zips, [16MB,32MB) sorted zips, [32MB,96MB) cub temp

static __device__ __forceinline__ uint32_t f32_to_ord(uint32_t b) {
    return b ^ ((uint32_t)((int32_t)b >> 31) | 0x80000000u);
}

__global__ void pack_kernel(const int* __restrict__ samp,
                            const int* __restrict__ ridx,
                            const float* __restrict__ grad,
                            const float* __restrict__ rval,
                            int S, int K, float adj,
                            uint32_t* __restrict__ keys,
                            uint32_t* __restrict__ vals) {
    int i = blockIdx.x * blockDim.x + threadIdx.x;
    if (i >= K) return;
    uint32_t key; float v;
    if (i < S) {
        key = (uint32_t)samp[i];
        v = fabsf(grad[i]);
    } else {
        int r = i - S;
        key = (uint32_t)ridx[2 * r] * (uint32_t)C_DIM + (uint32_t)ridx[2 * r + 1];
        v = adj * rval[r];
    }
    keys[i] = key;
    vals[i] = __float_as_uint(v);
}

// Per segment-head: sum values sequentially (stable sort1 => original order),
// emit zip = (~ord(sum) << 24) | key so ascending zip == (sum desc, key asc).
// Non-heads emit ~0 (never selected). Also histogram heads for threshold pick.
__global__ void headsum_kernel(const uint32_t* __restrict__ skeys,
                               const uint32_t* __restrict__ svals,
                               int K,
                               unsigned long long* __restrict__ out_zip,
                               uint32_t* __restrict__ hist) {
    int j = blockIdx.x * blockDim.x + threadIdx.x;
    if (j >= K) return;
    uint32_t key = skeys[j];
    bool head = (j == 0) || (skeys[j - 1] != key);
    if (!head) {
        out_zip[j] = ~0ull;
        return;
    }
    float sum = 0.0f;
    int t = j;
    while (t < K && skeys[t] == key) {
        sum += __uint_as_float(svals[t]);   // sequential, matches XLA scatter-add order
        ++t;
    }
    uint32_t ordk = ~f32_to_ord(__float_as_uint(sum));  // <= 0x7FFFFFFF (sum >= 0)
    out_zip[j] = ((unsigned long long)ordk << 24) | (unsigned long long)key;
    atomicAdd(&hist[ordk >> 13], 1u);
}

__global__ void coarse_kernel(const uint32_t* __restrict__ hist,
                              uint32_t* __restrict__ super) {
    typedef cub::BlockReduce<uint32_t, 256> BR;
    __shared__ typename BR::TempStorage ts;
    uint32_t v = hist[blockIdx.x * 256 + threadIdx.x];
    uint32_t s = BR(ts).Sum(v);
    if (threadIdx.x == 0) super[blockIdx.x] = s;
}

// Single block: smallest bin boundary B with #heads{ordkey < B} >= R.
__global__ void select_kernel(const uint32_t* __restrict__ super,
                              const uint32_t* __restrict__ hist,
                              uint32_t R, uint32_t* __restrict__ Bout) {
    typedef cub::BlockScan<uint32_t, 1024> BS;
    __shared__ typename BS::TempStorage ts;
    __shared__ uint32_t s_sb, s_base;
    if (threadIdx.x == 0) { s_sb = 0xFFFFFFFFu; s_base = 0; }
    __syncthreads();

    uint32_t v = super[threadIdx.x];
    uint32_t inc;
    BS(ts).InclusiveSum(v, inc);
    if (inc >= R && (inc - v) < R) {          // unique crossing superbin
        s_sb = threadIdx.x;
        s_base = inc - v;
    }
    __syncthreads();
    if (s_sb == 0xFFFFFFFFu) {                // pathological: fewer heads than R
        if (threadIdx.x == 0) Bout[0] = 0xFFFFFFFFu;
        return;
    }
    uint32_t sb = s_sb, base = s_base;
    __syncthreads();                          // before TempStorage reuse
    uint32_t h = (threadIdx.x < 256) ? hist[sb * 256 + threadIdx.x] : 0u;
    uint32_t inc1;
    BS(ts).InclusiveSum(h, inc1);
    if (threadIdx.x < 256) {
        uint32_t excl = inc1 - h;
        if (base + inc1 >= R && base + excl < R) {
            Bout[0] = ((sb * 256u + threadIdx.x) + 1u) << 13;
        }
    }
}

struct ZipLess {
    const uint32_t* B;
    __device__ __forceinline__ bool operator()(unsigned long long z) const {
        return z < ((unsigned long long)(*B) << 24);
    }
};

__global__ void output_kernel(const unsigned long long* __restrict__ szip,
                              int R, int write_idx, int write_val, int val_off,
                              float* __restrict__ out) {
    int r = blockIdx.x * blockDim.x + threadIdx.x;
    if (r >= R) return;
    unsigned long long z = szip[r];
    uint32_t key = (uint32_t)(z & 0xFFFFFFull);
    if (write_idx) {
        out[2 * r]     = (float)(key >> 12);
        out[2 * r + 1] = (float)(key & 4095u);
    }
    if (write_val) {
        uint32_t u = ~(uint32_t)(z >> 24);   // recover ord bits
        uint32_t b = (u & 0x80000000u) ? (u ^ 0x80000000u) : ~u;
        out[val_off + r] = __uint_as_float(b);
    }
}

extern "C" void kernel_launch(void* const* d_in, const int* in_sizes, int n_in,
                              void* d_out, int out_size) {
    (void)n_in;
    const int*   samp = (const int*)d_in[0];
    const int*   ridx = (const int*)d_in[1];
    const float* rval = (const float*)d_in[2];
    const float* grad = (const float*)d_in[3];

    int S = in_sizes[0];
    int R = in_sizes[2];
    int K = S + R;
    if (K > MAX_K) K = MAX_K;

    double frac = (double)S / NUMEL_D;
    float adj = (float)(1.0 - frac * (1.0 - 0.95));

    uint32_t *ka, *kb, *va, *vb, *hist, *super, *Bp;
    unsigned long long *zip;
    int *nump;
    unsigned char* arena;
    cudaGetSymbolAddress((void**)&ka, g_ka);
    cudaGetSymbolAddress((void**)&kb, g_kb);
    cudaGetSymbolAddress((void**)&va, g_va);
    cudaGetSymbolAddress((void**)&vb, g_vb);
    cudaGetSymbolAddress((void**)&zip, g_z);
    cudaGetSymbolAddress((void**)&hist, g_hist);
    cudaGetSymbolAddress((void**)&super, g_super);
    cudaGetSymbolAddress((void**)&Bp, g_B);
    cudaGetSymbolAddress((void**)&nump, g_num);
    cudaGetSymbolAddress((void**)&arena, g_temp);

    unsigned long long* cand   = (unsigned long long*)arena;               // 16MB
    unsigned long long* sorted = (unsigned long long*)(arena + (16u<<20)); // 16MB
    void* tmp = (void*)(arena + (32u<<20));
    const size_t TMPB = (size_t)64u << 20;

    const int BLK = 256;
    const int GK = (K + BLK - 1) / BLK;

    // 0) zero histogram (graph replays need re-init each launch)
    cudaMemsetAsync(hist, 0, HIST_BINS * sizeof(uint32_t));

    // 1) Build (key, value-bits)
    pack_kernel<<<GK, BLK>>>(samp, ridx, grad, rval, S, K, adj, ka, va);

    // 2) Stable sort by 24-bit key, payload = value bits (preserves original order per key)
    {
        size_t need = 0;
        cub::DeviceRadixSort::SortPairs(nullptr, need, ka, kb, va, vb, K, 0, 24);
        if (need <= TMPB)
            cub::DeviceRadixSort::SortPairs(tmp, need, ka, kb, va, vb, K, 0, 24);
    }

    // 3) Ordered per-segment sums -> zip per position + histogram of heads
    headsum_kernel<<<GK, BLK>>>(kb, vb, K, zip, hist);

    // 4) Threshold B (bin-granular, includes all ties of the R-th element)
    coarse_kernel<<<1024, 256>>>(hist, super);
    select_kernel<<<1, 1024>>>(super, hist, (uint32_t)R, Bp);

    // 5) Pad candidate buffer, then stable (order-preserving) selection of
    //    all zips below the threshold — keeps ascending-key order for ties.
    cudaMemsetAsync(cand, 0xFF, (size_t)M_SORT * sizeof(unsigned long long));
    {
        ZipLess op{Bp};
        size_t need = 0;
        cub::DeviceSelect::If(nullptr, need, zip, cand, nump, K, op);
        if (need <= TMPB)
            cub::DeviceSelect::If(tmp, need, zip, cand, nump, K, op);
    }

    // 6) Keys-only u64 sort on bits [24,55) (ordkey): stable => equal-ordkey
    //    candidates keep ascending-key order == lax.top_k tie-break.
    {
        size_t need = 0;
        cub::DeviceRadixSort::SortKeys(nullptr, need, cand, sorted, M_SORT, 24, 55);
        if (need <= TMPB)
            cub::DeviceRadixSort::SortKeys(tmp, need, cand, sorted, M_SORT, 24, 55);
    }

    // 7) Emit [new_index (R,2), top_vals (R)] as f32
    int write_idx = 1, write_val = 1, val_off = 2 * R;
    if (out_size == R)          { write_idx = 0; val_off = 0; }
    else if (out_size == 2 * R) { write_val = 0; }
    output_kernel<<<(R + BLK - 1) / BLK, BLK>>>(sorted, R, write_idx, write_val, val_off,
                                                (float*)d_out);
}